// round 3
// baseline (speedup 1.0000x reference)
#include <cuda_runtime.h>
#include <cstdint>

// ---------------- problem constants ----------------
#define NNODES 100000
#define NEDGES 800000
#define NGRAPH 64
#define SCAN_CHUNK 1024
#define SCAN_NB ((NNODES + SCAN_CHUNK - 1) / SCAN_CHUNK)   // 98

// ---------------- scratch (static device globals; no allocation) ----------------
// float4-typed so 16B alignment is guaranteed for vector access.
__device__ float4 g_bufA4[(size_t)NNODES * 32];   // 51.2 MB  (GEMM output h)
__device__ float4 g_bufB4[(size_t)NNODES * 32];   // 51.2 MB  (agg output)
__device__ float  g_dinv[NNODES];
__device__ int    g_cnti[NNODES];
__device__ int    g_off[NNODES + 1];
__device__ int    g_cursor[NNODES];
__device__ int    g_elist[NEDGES];
__device__ int    g_bsum[SCAN_NB];
__device__ int    g_bpre[SCAN_NB];
__device__ float  g_pool[NGRAPH * 128];
__device__ float  g_gcnt[NGRAPH];

// ---------------- zero counters / pool ----------------
__global__ void zero_misc_kernel() {
    int i = blockIdx.x * blockDim.x + threadIdx.x;
    int stride = gridDim.x * blockDim.x;
    for (int k = i; k < NNODES; k += stride) g_cnti[k] = 0;
    if (i < NGRAPH * 128) g_pool[i] = 0.f;
    if (i < NGRAPH) g_gcnt[i] = 0.f;
}

// ---------------- in-degree histogram (edge_index is INT32) ----------------
__global__ void count_kernel(const int* __restrict__ dst, int E) {
    int e = blockIdx.x * blockDim.x + threadIdx.x;
    if (e >= E) return;
    atomicAdd(&g_cnti[dst[e]], 1);
}

// ---------------- scan phase A: per-chunk sums ----------------
__global__ __launch_bounds__(256)
void scanA_kernel() {
    __shared__ int ssum[8];
    const int tid = threadIdx.x;
    const int base = blockIdx.x * SCAN_CHUNK + tid * 4;
    int s = 0;
#pragma unroll
    for (int j = 0; j < 4; j++) {
        int idx = base + j;
        if (idx < NNODES) s += g_cnti[idx];
    }
#pragma unroll
    for (int o = 16; o > 0; o >>= 1) s += __shfl_down_sync(0xffffffffu, s, o);
    if ((tid & 31) == 0) ssum[tid >> 5] = s;
    __syncthreads();
    if (tid == 0) {
        int t = 0;
#pragma unroll
        for (int w = 0; w < 8; w++) t += ssum[w];
        g_bsum[blockIdx.x] = t;
    }
}

// ---------------- scan phase B: scan chunk sums (1 block) ----------------
__global__ __launch_bounds__(128)
void scanB_kernel() {
    __shared__ int sh[128];
    const int t = threadIdx.x;
    int v = (t < SCAN_NB) ? g_bsum[t] : 0;
    sh[t] = v;
    __syncthreads();
    for (int o = 1; o < 128; o <<= 1) {
        int add = (t >= o) ? sh[t - o] : 0;
        __syncthreads();
        sh[t] += add;
        __syncthreads();
    }
    if (t < SCAN_NB) g_bpre[t] = sh[t] - v;       // exclusive
    if (t == SCAN_NB - 1) g_off[NNODES] = sh[t];  // total = E
}

// ---------------- scan phase C: per-chunk exclusive scan -> offsets, cursor, dinv ----------------
__global__ __launch_bounds__(256)
void scanC_kernel() {
    __shared__ int warpsum[8];
    const int tid = threadIdx.x;
    const int lane = tid & 31;
    const int warp = tid >> 5;
    const int base = blockIdx.x * SCAN_CHUNK + tid * 4;

    int v[4];
    int t = 0;
#pragma unroll
    for (int j = 0; j < 4; j++) {
        int idx = base + j;
        v[j] = (idx < NNODES) ? g_cnti[idx] : 0;
        t += v[j];
    }
    int incl = t;
#pragma unroll
    for (int o = 1; o < 32; o <<= 1) {
        int n = __shfl_up_sync(0xffffffffu, incl, o);
        if (lane >= o) incl += n;
    }
    if (lane == 31) warpsum[warp] = incl;
    __syncthreads();
    if (tid == 0) {
        int run = 0;
#pragma unroll
        for (int w = 0; w < 8; w++) { int x = warpsum[w]; warpsum[w] = run; run += x; }
    }
    __syncthreads();
    int run = g_bpre[blockIdx.x] + warpsum[warp] + (incl - t);
#pragma unroll
    for (int j = 0; j < 4; j++) {
        int idx = base + j;
        if (idx < NNODES) {
            g_off[idx] = run;
            g_cursor[idx] = run;
            g_dinv[idx] = rsqrtf((float)v[j] + 1.0f);   // +1 self-loop
            run += v[j];
        }
    }
}

// ---------------- fill edge lists (CSR) ----------------
__global__ void fill_kernel(const int* __restrict__ src,
                            const int* __restrict__ dst, int E) {
    int e = blockIdx.x * blockDim.x + threadIdx.x;
    if (e >= E) return;
    int d = dst[e];
    int pos = atomicAdd(&g_cursor[d], 1);
    g_elist[pos] = src[e];
}

// ---------------- SGEMM: g_bufA[M,128] = A[M,128] @ B[128,128] ----------------
// BM=128, BN=128, BK=8, 256 threads, 8x8 per-thread microtile. A = ext or g_bufB.
__global__ __launch_bounds__(256)
void sgemm128_kernel(const float* __restrict__ Aext, int useExt,
                     const float* __restrict__ B, int M) {
    __shared__ alignas(16) float As[8][128];   // [k][m]
    __shared__ alignas(16) float Bs[8][128];   // [k][n]

    const float* __restrict__ A = useExt ? Aext : reinterpret_cast<const float*>(g_bufB4);
    float4* __restrict__ C4 = g_bufA4;

    const int tid = threadIdx.x;
    const int block_row = blockIdx.x * 128;
    const int tr = tid / 16;
    const int tc = tid % 16;
    const int a_row = tid >> 1;
    const int a_col = (tid & 1) * 4;
    const int b_row = tid >> 5;
    const int b_col = (tid & 31) * 4;

    float acc[8][8];
#pragma unroll
    for (int i = 0; i < 8; i++)
#pragma unroll
        for (int j = 0; j < 8; j++) acc[i][j] = 0.f;

    for (int k0 = 0; k0 < 128; k0 += 8) {
        float4 av = make_float4(0.f, 0.f, 0.f, 0.f);
        const int gr = block_row + a_row;
        if (gr < M)
            av = *reinterpret_cast<const float4*>(A + (size_t)gr * 128 + k0 + a_col);
        As[a_col + 0][a_row] = av.x;
        As[a_col + 1][a_row] = av.y;
        As[a_col + 2][a_row] = av.z;
        As[a_col + 3][a_row] = av.w;

        *reinterpret_cast<float4*>(&Bs[b_row][b_col]) =
            *reinterpret_cast<const float4*>(B + (size_t)(k0 + b_row) * 128 + b_col);

        __syncthreads();

#pragma unroll
        for (int kk = 0; kk < 8; kk++) {
            float ar[8], br[8];
            *reinterpret_cast<float4*>(&ar[0]) = *reinterpret_cast<const float4*>(&As[kk][tr * 8]);
            *reinterpret_cast<float4*>(&ar[4]) = *reinterpret_cast<const float4*>(&As[kk][tr * 8 + 4]);
            *reinterpret_cast<float4*>(&br[0]) = *reinterpret_cast<const float4*>(&Bs[kk][tc * 8]);
            *reinterpret_cast<float4*>(&br[4]) = *reinterpret_cast<const float4*>(&Bs[kk][tc * 8 + 4]);
#pragma unroll
            for (int i = 0; i < 8; i++)
#pragma unroll
                for (int j = 0; j < 8; j++)
                    acc[i][j] = fmaf(ar[i], br[j], acc[i][j]);
        }
        __syncthreads();
    }

#pragma unroll
    for (int i = 0; i < 8; i++) {
        const int row = block_row + tr * 8 + i;
        if (row < M) {
            C4[(size_t)row * 32 + tc * 2]     = make_float4(acc[i][0], acc[i][1], acc[i][2], acc[i][3]);
            C4[(size_t)row * 32 + tc * 2 + 1] = make_float4(acc[i][4], acc[i][5], acc[i][6], acc[i][7]);
        }
    }
}

// ---------------- gather aggregation + self-loop + bias + ReLU ----------------
// One warp per destination node; lane handles one float4 (32*4 = 128 feats).
// reads g_bufA4, writes g_bufB4.
__global__ __launch_bounds__(256)
void agg_gather_kernel(const float* __restrict__ bias) {
    const int node = (blockIdx.x * blockDim.x + threadIdx.x) >> 5;
    const int lane = threadIdx.x & 31;
    if (node >= NNODES) return;

    const float4* __restrict__ h4 = g_bufA4;
    const float dd = g_dinv[node];

    // self loop: dinv[d]^2 * h[d]
    float4 hv = h4[(size_t)node * 32 + lane];
    const float ws = dd * dd;
    float4 acc;
    acc.x = ws * hv.x; acc.y = ws * hv.y; acc.z = ws * hv.z; acc.w = ws * hv.w;

    const int beg = g_off[node];
    const int end = g_off[node + 1];
    for (int i = beg; i < end; i++) {
        const int s = g_elist[i];                 // broadcast load
        const float w = dd * g_dinv[s];
        const float4 v = h4[(size_t)s * 32 + lane];
        acc.x = fmaf(w, v.x, acc.x);
        acc.y = fmaf(w, v.y, acc.y);
        acc.z = fmaf(w, v.z, acc.z);
        acc.w = fmaf(w, v.w, acc.w);
    }

    const float4 bv = reinterpret_cast<const float4*>(bias)[lane];
    acc.x = fmaxf(acc.x + bv.x, 0.f);
    acc.y = fmaxf(acc.y + bv.y, 0.f);
    acc.z = fmaxf(acc.z + bv.z, 0.f);
    acc.w = fmaxf(acc.w + bv.w, 0.f);
    g_bufB4[(size_t)node * 32 + lane] = acc;
}

// ---------------- pooling: sorted batch ids -> register accumulate, flush on change ----------------
#define POOL_NODES_PER_BLOCK 256
__global__ __launch_bounds__(128)
void pool_kernel(const int* __restrict__ batch, int N) {
    const int n0 = blockIdx.x * POOL_NODES_PER_BLOCK;
    const int n1 = min(n0 + POOL_NODES_PER_BLOCK, N);
    const int d = threadIdx.x;
    const float* __restrict__ h = reinterpret_cast<const float*>(g_bufB4);

    float acc = 0.f, c = 0.f;
    int curg = -1;
    for (int n = n0; n < n1; n++) {
        const int g = batch[n];
        if (g != curg) {
            if (curg >= 0) {
                atomicAdd(&g_pool[curg * 128 + d], acc);
                if (d == 0) atomicAdd(&g_gcnt[curg], c);
            }
            curg = g; acc = 0.f; c = 0.f;
        }
        acc += h[(size_t)n * 128 + d];
        c += 1.f;
    }
    if (curg >= 0) {
        atomicAdd(&g_pool[curg * 128 + d], acc);
        if (d == 0) atomicAdd(&g_gcnt[curg], c);
    }
}

// ---------------- FC head ----------------
__global__ __launch_bounds__(128)
void fc_kernel(const float* __restrict__ W, const float* __restrict__ b,
               float* __restrict__ out) {
    __shared__ float row[128];
    const int g = blockIdx.x;
    const int j = threadIdx.x;
    const float inv = 1.0f / fmaxf(g_gcnt[g], 1.0f);
    row[j] = g_pool[g * 128 + j] * inv;
    __syncthreads();
    float acc = b[j];
#pragma unroll
    for (int k = 0; k < 128; k++)
        acc = fmaf(row[k], W[k * 128 + j], acc);
    out[g * 128 + j] = acc;
}

// ---------------- launch ----------------
extern "C" void kernel_launch(void* const* d_in, const int* in_sizes, int n_in,
                              void* d_out, int out_size) {
    const float* x   = (const float*)d_in[0];
    const int*   ei  = (const int*)d_in[1];    // int32! (JAX x64 disabled)
    const int*   bat = (const int*)d_in[2];    // int32!
    const float* W1  = (const float*)d_in[3];
    const float* b1  = (const float*)d_in[4];
    const float* W2  = (const float*)d_in[5];
    const float* b2  = (const float*)d_in[6];
    const float* Wfc = (const float*)d_in[7];
    const float* bfc = (const float*)d_in[8];
    float*       out = (float*)d_out;

    const int N = in_sizes[2];
    const int E = in_sizes[1] / 2;
    const int* src = ei;
    const int* dst = ei + E;

    // --- CSR build (reused by both layers) ---
    zero_misc_kernel<<<1184, 256>>>();
    count_kernel<<<(E + 255) / 256, 256>>>(dst, E);
    scanA_kernel<<<SCAN_NB, 256>>>();
    scanB_kernel<<<1, 128>>>();
    scanC_kernel<<<SCAN_NB, 256>>>();
    fill_kernel<<<(E + 255) / 256, 256>>>(src, dst, E);

    const int gemm_blocks = (N + 127) / 128;
    const int agg_blocks  = (N * 32 + 255) / 256;   // warp per node

    // --- layer 1 ---
    sgemm128_kernel<<<gemm_blocks, 256>>>(x, 1, W1, N);
    agg_gather_kernel<<<agg_blocks, 256>>>(b1);

    // --- layer 2 ---
    sgemm128_kernel<<<gemm_blocks, 256>>>(nullptr, 0, W2, N);
    agg_gather_kernel<<<agg_blocks, 256>>>(b2);

    // --- pool + fc ---
    pool_kernel<<<(N + POOL_NODES_PER_BLOCK - 1) / POOL_NODES_PER_BLOCK, 128>>>(bat, N);
    fc_kernel<<<NGRAPH, 128>>>(Wfc, bfc, out);
}

// round 4
// speedup vs baseline: 1.0036x; 1.0036x over previous
#include <cuda_runtime.h>
#include <cstdint>

// ---------------- problem constants ----------------
#define NNODES 100000
#define NEDGES 800000
#define NGRAPH 64
#define SCAN_CHUNK 1024
#define SCAN_NB ((NNODES + SCAN_CHUNK - 1) / SCAN_CHUNK)   // 98

// ---------------- scratch (static device globals; no allocation) ----------------
__device__ float4 g_bufA4[(size_t)NNODES * 32];   // 51.2 MB  (GEMM output h)
__device__ float4 g_bufB4[(size_t)NNODES * 32];   // 51.2 MB  (agg output)
__device__ float  g_dinv[NNODES];
__device__ int    g_cnti[NNODES];
__device__ int    g_off[NNODES + 1];
__device__ int    g_cursor[NNODES];
__device__ int    g_elist[NEDGES];
__device__ int    g_bsum[SCAN_NB];
__device__ int    g_bpre[SCAN_NB];
__device__ float  g_pool[NGRAPH * 128];
__device__ float  g_gcnt[NGRAPH];

// ---------------- zero counters / pool ----------------
__global__ void zero_misc_kernel() {
    int i = blockIdx.x * blockDim.x + threadIdx.x;
    int stride = gridDim.x * blockDim.x;
    for (int k = i; k < NNODES; k += stride) g_cnti[k] = 0;
    if (i < NGRAPH * 128) g_pool[i] = 0.f;
    if (i < NGRAPH) g_gcnt[i] = 0.f;
}

// ---------------- in-degree histogram (edge_index is INT32) ----------------
__global__ void count_kernel(const int* __restrict__ dst, int E) {
    int e = blockIdx.x * blockDim.x + threadIdx.x;
    if (e >= E) return;
    atomicAdd(&g_cnti[dst[e]], 1);
}

// ---------------- scan phase A: per-chunk sums ----------------
__global__ __launch_bounds__(256)
void scanA_kernel() {
    __shared__ int ssum[8];
    const int tid = threadIdx.x;
    const int base = blockIdx.x * SCAN_CHUNK + tid * 4;
    int s = 0;
#pragma unroll
    for (int j = 0; j < 4; j++) {
        int idx = base + j;
        if (idx < NNODES) s += g_cnti[idx];
    }
#pragma unroll
    for (int o = 16; o > 0; o >>= 1) s += __shfl_down_sync(0xffffffffu, s, o);
    if ((tid & 31) == 0) ssum[tid >> 5] = s;
    __syncthreads();
    if (tid == 0) {
        int t = 0;
#pragma unroll
        for (int w = 0; w < 8; w++) t += ssum[w];
        g_bsum[blockIdx.x] = t;
    }
}

// ---------------- scan phase B: scan chunk sums (1 block) ----------------
__global__ __launch_bounds__(128)
void scanB_kernel() {
    __shared__ int sh[128];
    const int t = threadIdx.x;
    int v = (t < SCAN_NB) ? g_bsum[t] : 0;
    sh[t] = v;
    __syncthreads();
    for (int o = 1; o < 128; o <<= 1) {
        int add = (t >= o) ? sh[t - o] : 0;
        __syncthreads();
        sh[t] += add;
        __syncthreads();
    }
    if (t < SCAN_NB) g_bpre[t] = sh[t] - v;       // exclusive
    if (t == SCAN_NB - 1) g_off[NNODES] = sh[t];  // total = E
}

// ---------------- scan phase C: per-chunk exclusive scan -> offsets, cursor, dinv ----------------
__global__ __launch_bounds__(256)
void scanC_kernel() {
    __shared__ int warpsum[8];
    const int tid = threadIdx.x;
    const int lane = tid & 31;
    const int warp = tid >> 5;
    const int base = blockIdx.x * SCAN_CHUNK + tid * 4;

    int v[4];
    int t = 0;
#pragma unroll
    for (int j = 0; j < 4; j++) {
        int idx = base + j;
        v[j] = (idx < NNODES) ? g_cnti[idx] : 0;
        t += v[j];
    }
    int incl = t;
#pragma unroll
    for (int o = 1; o < 32; o <<= 1) {
        int n = __shfl_up_sync(0xffffffffu, incl, o);
        if (lane >= o) incl += n;
    }
    if (lane == 31) warpsum[warp] = incl;
    __syncthreads();
    if (tid == 0) {
        int run = 0;
#pragma unroll
        for (int w = 0; w < 8; w++) { int x = warpsum[w]; warpsum[w] = run; run += x; }
    }
    __syncthreads();
    int run = g_bpre[blockIdx.x] + warpsum[warp] + (incl - t);
#pragma unroll
    for (int j = 0; j < 4; j++) {
        int idx = base + j;
        if (idx < NNODES) {
            g_off[idx] = run;
            g_cursor[idx] = run;
            g_dinv[idx] = rsqrtf((float)v[j] + 1.0f);   // +1 self-loop
            run += v[j];
        }
    }
}

// ---------------- fill edge lists (CSR) ----------------
__global__ void fill_kernel(const int* __restrict__ src,
                            const int* __restrict__ dst, int E) {
    int e = blockIdx.x * blockDim.x + threadIdx.x;
    if (e >= E) return;
    int d = dst[e];
    int pos = atomicAdd(&g_cursor[d], 1);
    g_elist[pos] = src[e];
}

// ---------------- SGEMM with packed fma.rn.f32x2 ----------------
// g_bufA[M,128] = A[M,128] @ B[128,128]; BM=128, BN=128, BK=8, 256 threads,
// 8x8 per-thread microtile held as 8 rows x 4 packed-f32x2 accumulators.
__global__ __launch_bounds__(256)
void sgemm128_kernel(const float* __restrict__ Aext, int useExt,
                     const float* __restrict__ B, int M) {
    __shared__ alignas(16) float As[8][128];   // [k][m]
    __shared__ alignas(16) float Bs[8][128];   // [k][n]

    const float* __restrict__ A = useExt ? Aext : reinterpret_cast<const float*>(g_bufB4);
    float4* __restrict__ C4 = g_bufA4;

    const int tid = threadIdx.x;
    const int block_row = blockIdx.x * 128;
    const int tr = tid / 16;
    const int tc = tid % 16;
    const int a_row = tid >> 1;
    const int a_col = (tid & 1) * 4;
    const int b_row = tid >> 5;
    const int b_col = (tid & 31) * 4;

    // packed accumulators: acc2[i][j] holds columns (2j, 2j+1) of row i
    long long acc2[8][4];
#pragma unroll
    for (int i = 0; i < 8; i++)
#pragma unroll
        for (int j = 0; j < 4; j++) acc2[i][j] = 0ll;

    for (int k0 = 0; k0 < 128; k0 += 8) {
        float4 av = make_float4(0.f, 0.f, 0.f, 0.f);
        const int gr = block_row + a_row;
        if (gr < M)
            av = *reinterpret_cast<const float4*>(A + (size_t)gr * 128 + k0 + a_col);
        As[a_col + 0][a_row] = av.x;
        As[a_col + 1][a_row] = av.y;
        As[a_col + 2][a_row] = av.z;
        As[a_col + 3][a_row] = av.w;

        *reinterpret_cast<float4*>(&Bs[b_row][b_col]) =
            *reinterpret_cast<const float4*>(B + (size_t)(k0 + b_row) * 128 + b_col);

        __syncthreads();

#pragma unroll
        for (int kk = 0; kk < 8; kk++) {
            float ar[8];
            *reinterpret_cast<float4*>(&ar[0]) = *reinterpret_cast<const float4*>(&As[kk][tr * 8]);
            *reinterpret_cast<float4*>(&ar[4]) = *reinterpret_cast<const float4*>(&As[kk][tr * 8 + 4]);

            long long br2[4];
            {
                longlong2 t0 = *reinterpret_cast<const longlong2*>(&Bs[kk][tc * 8]);
                longlong2 t1 = *reinterpret_cast<const longlong2*>(&Bs[kk][tc * 8 + 4]);
                br2[0] = t0.x; br2[1] = t0.y; br2[2] = t1.x; br2[3] = t1.y;
            }

#pragma unroll
            for (int i = 0; i < 8; i++) {
                unsigned int ab = __float_as_uint(ar[i]);
                long long a2;
                asm("mov.b64 %0, {%1, %1};" : "=l"(a2) : "r"(ab));
#pragma unroll
                for (int j = 0; j < 4; j++) {
                    asm("fma.rn.f32x2 %0, %1, %2, %0;"
                        : "+l"(acc2[i][j]) : "l"(a2), "l"(br2[j]));
                }
            }
        }
        __syncthreads();
    }

#pragma unroll
    for (int i = 0; i < 8; i++) {
        const int row = block_row + tr * 8 + i;
        if (row < M) {
            float2 p0 = *reinterpret_cast<float2*>(&acc2[i][0]);
            float2 p1 = *reinterpret_cast<float2*>(&acc2[i][1]);
            float2 p2 = *reinterpret_cast<float2*>(&acc2[i][2]);
            float2 p3 = *reinterpret_cast<float2*>(&acc2[i][3]);
            C4[(size_t)row * 32 + tc * 2]     = make_float4(p0.x, p0.y, p1.x, p1.y);
            C4[(size_t)row * 32 + tc * 2 + 1] = make_float4(p2.x, p2.y, p3.x, p3.y);
        }
    }
}

// ---------------- gather aggregation + self-loop + bias + ReLU ----------------
// One warp per destination node; lane handles one float4. 2-way unrolled for MLP.
__global__ __launch_bounds__(256)
void agg_gather_kernel(const float* __restrict__ bias) {
    const int node = (blockIdx.x * blockDim.x + threadIdx.x) >> 5;
    const int lane = threadIdx.x & 31;
    if (node >= NNODES) return;

    const float4* __restrict__ h4 = g_bufA4;
    const float dd = g_dinv[node];

    // self loop: dinv[d]^2 * h[d]
    float4 hv = h4[(size_t)node * 32 + lane];
    const float ws = dd * dd;
    float4 acc;
    acc.x = ws * hv.x; acc.y = ws * hv.y; acc.z = ws * hv.z; acc.w = ws * hv.w;

    const int beg = g_off[node];
    const int end = g_off[node + 1];
    int i = beg;
    for (; i + 1 < end; i += 2) {
        const int s0 = g_elist[i];
        const int s1 = g_elist[i + 1];
        const float w0 = dd * g_dinv[s0];
        const float w1 = dd * g_dinv[s1];
        const float4 v0 = h4[(size_t)s0 * 32 + lane];
        const float4 v1 = h4[(size_t)s1 * 32 + lane];
        acc.x = fmaf(w0, v0.x, acc.x);
        acc.y = fmaf(w0, v0.y, acc.y);
        acc.z = fmaf(w0, v0.z, acc.z);
        acc.w = fmaf(w0, v0.w, acc.w);
        acc.x = fmaf(w1, v1.x, acc.x);
        acc.y = fmaf(w1, v1.y, acc.y);
        acc.z = fmaf(w1, v1.z, acc.z);
        acc.w = fmaf(w1, v1.w, acc.w);
    }
    if (i < end) {
        const int s = g_elist[i];
        const float w = dd * g_dinv[s];
        const float4 v = h4[(size_t)s * 32 + lane];
        acc.x = fmaf(w, v.x, acc.x);
        acc.y = fmaf(w, v.y, acc.y);
        acc.z = fmaf(w, v.z, acc.z);
        acc.w = fmaf(w, v.w, acc.w);
    }

    const float4 bv = reinterpret_cast<const float4*>(bias)[lane];
    acc.x = fmaxf(acc.x + bv.x, 0.f);
    acc.y = fmaxf(acc.y + bv.y, 0.f);
    acc.z = fmaxf(acc.z + bv.z, 0.f);
    acc.w = fmaxf(acc.w + bv.w, 0.f);
    g_bufB4[(size_t)node * 32 + lane] = acc;
}

// ---------------- pooling: sorted batch ids -> register accumulate, flush on change ----------------
#define POOL_NODES_PER_BLOCK 256
__global__ __launch_bounds__(128)
void pool_kernel(const int* __restrict__ batch, int N) {
    const int n0 = blockIdx.x * POOL_NODES_PER_BLOCK;
    const int n1 = min(n0 + POOL_NODES_PER_BLOCK, N);
    const int d = threadIdx.x;
    const float* __restrict__ h = reinterpret_cast<const float*>(g_bufB4);

    float acc = 0.f, c = 0.f;
    int curg = -1;
    for (int n = n0; n < n1; n++) {
        const int g = batch[n];
        if (g != curg) {
            if (curg >= 0) {
                atomicAdd(&g_pool[curg * 128 + d], acc);
                if (d == 0) atomicAdd(&g_gcnt[curg], c);
            }
            curg = g; acc = 0.f; c = 0.f;
        }
        acc += h[(size_t)n * 128 + d];
        c += 1.f;
    }
    if (curg >= 0) {
        atomicAdd(&g_pool[curg * 128 + d], acc);
        if (d == 0) atomicAdd(&g_gcnt[curg], c);
    }
}

// ---------------- FC head ----------------
__global__ __launch_bounds__(128)
void fc_kernel(const float* __restrict__ W, const float* __restrict__ b,
               float* __restrict__ out) {
    __shared__ float row[128];
    const int g = blockIdx.x;
    const int j = threadIdx.x;
    const float inv = 1.0f / fmaxf(g_gcnt[g], 1.0f);
    row[j] = g_pool[g * 128 + j] * inv;
    __syncthreads();
    float acc = b[j];
#pragma unroll
    for (int k = 0; k < 128; k++)
        acc = fmaf(row[k], W[k * 128 + j], acc);
    out[g * 128 + j] = acc;
}

// ---------------- launch ----------------
extern "C" void kernel_launch(void* const* d_in, const int* in_sizes, int n_in,
                              void* d_out, int out_size) {
    const float* x   = (const float*)d_in[0];
    const int*   ei  = (const int*)d_in[1];    // int32 (JAX x64 disabled)
    const int*   bat = (const int*)d_in[2];
    const float* W1  = (const float*)d_in[3];
    const float* b1  = (const float*)d_in[4];
    const float* W2  = (const float*)d_in[5];
    const float* b2  = (const float*)d_in[6];
    const float* Wfc = (const float*)d_in[7];
    const float* bfc = (const float*)d_in[8];
    float*       out = (float*)d_out;

    const int N = in_sizes[2];
    const int E = in_sizes[1] / 2;
    const int* src = ei;
    const int* dst = ei + E;

    // --- CSR build (reused by both layers) ---
    zero_misc_kernel<<<1184, 256>>>();
    count_kernel<<<(E + 255) / 256, 256>>>(dst, E);
    scanA_kernel<<<SCAN_NB, 256>>>();
    scanB_kernel<<<1, 128>>>();
    scanC_kernel<<<SCAN_NB, 256>>>();
    fill_kernel<<<(E + 255) / 256, 256>>>(src, dst, E);

    const int gemm_blocks = (N + 127) / 128;
    const int agg_blocks  = (N * 32 + 255) / 256;   // warp per node

    // --- layer 1 ---
    sgemm128_kernel<<<gemm_blocks, 256>>>(x, 1, W1, N);
    agg_gather_kernel<<<agg_blocks, 256>>>(b1);

    // --- layer 2 ---
    sgemm128_kernel<<<gemm_blocks, 256>>>(nullptr, 0, W2, N);
    agg_gather_kernel<<<agg_blocks, 256>>>(b2);

    // --- pool + fc ---
    pool_kernel<<<(N + POOL_NODES_PER_BLOCK - 1) / POOL_NODES_PER_BLOCK, 128>>>(bat, N);
    fc_kernel<<<NGRAPH, 128>>>(Wfc, bfc, out);
}

// round 5
// speedup vs baseline: 1.1757x; 1.1715x over previous
#include <cuda_runtime.h>
#include <cstdint>

// ---------------- problem constants ----------------
#define NNODES 100000
#define NEDGES 800000
#define NGRAPH 64
#define SCAN_CHUNK 1024
#define SCAN_NB ((NNODES + SCAN_CHUNK - 1) / SCAN_CHUNK)   // 98

// ---------------- scratch (static device globals; no allocation) ----------------
__device__ float4 g_bufA4[(size_t)NNODES * 32];   // 51.2 MB  (GEMM output h)
__device__ float4 g_bufB4[(size_t)NNODES * 32];   // 51.2 MB  (agg output)
__device__ float  g_dinv[NNODES];
__device__ int    g_cnti[NNODES];
__device__ int    g_off[NNODES + 1];
__device__ int    g_cursor[NNODES];
__device__ int    g_elist[NEDGES];
__device__ int    g_bsum[SCAN_NB];
__device__ int    g_bpre[SCAN_NB];
__device__ float  g_pool[NGRAPH * 128];
__device__ float  g_gcnt[NGRAPH];

// ---------------- zero counters / pool ----------------
__global__ void zero_misc_kernel() {
    int i = blockIdx.x * blockDim.x + threadIdx.x;
    int stride = gridDim.x * blockDim.x;
    for (int k = i; k < NNODES; k += stride) g_cnti[k] = 0;
    if (i < NGRAPH * 128) g_pool[i] = 0.f;
    if (i < NGRAPH) g_gcnt[i] = 0.f;
}

// ---------------- in-degree histogram (edge_index is INT32) ----------------
__global__ void count_kernel(const int* __restrict__ dst, int E) {
    int e = blockIdx.x * blockDim.x + threadIdx.x;
    if (e >= E) return;
    atomicAdd(&g_cnti[dst[e]], 1);
}

// ---------------- scan phase A: per-chunk sums ----------------
__global__ __launch_bounds__(256)
void scanA_kernel() {
    __shared__ int ssum[8];
    const int tid = threadIdx.x;
    const int base = blockIdx.x * SCAN_CHUNK + tid * 4;
    int s = 0;
#pragma unroll
    for (int j = 0; j < 4; j++) {
        int idx = base + j;
        if (idx < NNODES) s += g_cnti[idx];
    }
#pragma unroll
    for (int o = 16; o > 0; o >>= 1) s += __shfl_down_sync(0xffffffffu, s, o);
    if ((tid & 31) == 0) ssum[tid >> 5] = s;
    __syncthreads();
    if (tid == 0) {
        int t = 0;
#pragma unroll
        for (int w = 0; w < 8; w++) t += ssum[w];
        g_bsum[blockIdx.x] = t;
    }
}

// ---------------- scan phase B: scan chunk sums (1 block) ----------------
__global__ __launch_bounds__(128)
void scanB_kernel() {
    __shared__ int sh[128];
    const int t = threadIdx.x;
    int v = (t < SCAN_NB) ? g_bsum[t] : 0;
    sh[t] = v;
    __syncthreads();
    for (int o = 1; o < 128; o <<= 1) {
        int add = (t >= o) ? sh[t - o] : 0;
        __syncthreads();
        sh[t] += add;
        __syncthreads();
    }
    if (t < SCAN_NB) g_bpre[t] = sh[t] - v;       // exclusive
    if (t == SCAN_NB - 1) g_off[NNODES] = sh[t];  // total = E
}

// ---------------- scan phase C: per-chunk exclusive scan -> offsets, cursor, dinv ----------------
__global__ __launch_bounds__(256)
void scanC_kernel() {
    __shared__ int warpsum[8];
    const int tid = threadIdx.x;
    const int lane = tid & 31;
    const int warp = tid >> 5;
    const int base = blockIdx.x * SCAN_CHUNK + tid * 4;

    int v[4];
    int t = 0;
#pragma unroll
    for (int j = 0; j < 4; j++) {
        int idx = base + j;
        v[j] = (idx < NNODES) ? g_cnti[idx] : 0;
        t += v[j];
    }
    int incl = t;
#pragma unroll
    for (int o = 1; o < 32; o <<= 1) {
        int n = __shfl_up_sync(0xffffffffu, incl, o);
        if (lane >= o) incl += n;
    }
    if (lane == 31) warpsum[warp] = incl;
    __syncthreads();
    if (tid == 0) {
        int run = 0;
#pragma unroll
        for (int w = 0; w < 8; w++) { int x = warpsum[w]; warpsum[w] = run; run += x; }
    }
    __syncthreads();
    int run = g_bpre[blockIdx.x] + warpsum[warp] + (incl - t);
#pragma unroll
    for (int j = 0; j < 4; j++) {
        int idx = base + j;
        if (idx < NNODES) {
            g_off[idx] = run;
            g_cursor[idx] = run;
            g_dinv[idx] = rsqrtf((float)v[j] + 1.0f);   // +1 self-loop
            run += v[j];
        }
    }
}

// ---------------- fill edge lists (CSR) ----------------
__global__ void fill_kernel(const int* __restrict__ src,
                            const int* __restrict__ dst, int E) {
    int e = blockIdx.x * blockDim.x + threadIdx.x;
    if (e >= E) return;
    int d = dst[e];
    int pos = atomicAdd(&g_cursor[d], 1);
    g_elist[pos] = src[e];
}

// ---------------- SGEMM with packed fma.rn.f32x2 ----------------
// g_bufA[M,128] = A[M,128] @ B[128,128]; BM=128, BN=128, BK=8, 256 threads,
// 8x8 per-thread microtile held as 8 rows x 4 packed-f32x2 accumulators.
__global__ __launch_bounds__(256)
void sgemm128_kernel(const float* __restrict__ Aext, int useExt,
                     const float* __restrict__ B, int M) {
    __shared__ alignas(16) float As[8][128];   // [k][m]
    __shared__ alignas(16) float Bs[8][128];   // [k][n]

    const float* __restrict__ A = useExt ? Aext : reinterpret_cast<const float*>(g_bufB4);
    float4* __restrict__ C4 = g_bufA4;

    const int tid = threadIdx.x;
    const int block_row = blockIdx.x * 128;
    const int tr = tid / 16;
    const int tc = tid % 16;
    const int a_row = tid >> 1;
    const int a_col = (tid & 1) * 4;
    const int b_row = tid >> 5;
    const int b_col = (tid & 31) * 4;

    long long acc2[8][4];
#pragma unroll
    for (int i = 0; i < 8; i++)
#pragma unroll
        for (int j = 0; j < 4; j++) acc2[i][j] = 0ll;

    for (int k0 = 0; k0 < 128; k0 += 8) {
        float4 av = make_float4(0.f, 0.f, 0.f, 0.f);
        const int gr = block_row + a_row;
        if (gr < M)
            av = *reinterpret_cast<const float4*>(A + (size_t)gr * 128 + k0 + a_col);
        As[a_col + 0][a_row] = av.x;
        As[a_col + 1][a_row] = av.y;
        As[a_col + 2][a_row] = av.z;
        As[a_col + 3][a_row] = av.w;

        *reinterpret_cast<float4*>(&Bs[b_row][b_col]) =
            *reinterpret_cast<const float4*>(B + (size_t)(k0 + b_row) * 128 + b_col);

        __syncthreads();

#pragma unroll
        for (int kk = 0; kk < 8; kk++) {
            float ar[8];
            *reinterpret_cast<float4*>(&ar[0]) = *reinterpret_cast<const float4*>(&As[kk][tr * 8]);
            *reinterpret_cast<float4*>(&ar[4]) = *reinterpret_cast<const float4*>(&As[kk][tr * 8 + 4]);

            long long br2[4];
            {
                longlong2 t0 = *reinterpret_cast<const longlong2*>(&Bs[kk][tc * 8]);
                longlong2 t1 = *reinterpret_cast<const longlong2*>(&Bs[kk][tc * 8 + 4]);
                br2[0] = t0.x; br2[1] = t0.y; br2[2] = t1.x; br2[3] = t1.y;
            }

#pragma unroll
            for (int i = 0; i < 8; i++) {
                unsigned int ab = __float_as_uint(ar[i]);
                long long a2;
                asm("mov.b64 %0, {%1, %1};" : "=l"(a2) : "r"(ab));
#pragma unroll
                for (int j = 0; j < 4; j++) {
                    asm("fma.rn.f32x2 %0, %1, %2, %0;"
                        : "+l"(acc2[i][j]) : "l"(a2), "l"(br2[j]));
                }
            }
        }
        __syncthreads();
    }

#pragma unroll
    for (int i = 0; i < 8; i++) {
        const int row = block_row + tr * 8 + i;
        if (row < M) {
            float2 p0 = *reinterpret_cast<float2*>(&acc2[i][0]);
            float2 p1 = *reinterpret_cast<float2*>(&acc2[i][1]);
            float2 p2 = *reinterpret_cast<float2*>(&acc2[i][2]);
            float2 p3 = *reinterpret_cast<float2*>(&acc2[i][3]);
            C4[(size_t)row * 32 + tc * 2]     = make_float4(p0.x, p0.y, p1.x, p1.y);
            C4[(size_t)row * 32 + tc * 2 + 1] = make_float4(p2.x, p2.y, p3.x, p3.y);
        }
    }
}

// ---------------- gather aggregation + self-loop + bias + ReLU ----------------
// One warp per destination node; lane handles one float4. 4-way MLP batching.
__global__ __launch_bounds__(256)
void agg_gather_kernel(const float* __restrict__ bias) {
    const int node = (blockIdx.x * blockDim.x + threadIdx.x) >> 5;
    const int lane = threadIdx.x & 31;
    if (node >= NNODES) return;

    const float4* __restrict__ h4 = g_bufA4;
    const float dd = g_dinv[node];

    // self loop: dinv[d]^2 * h[d]
    float4 hv = h4[(size_t)node * 32 + lane];
    const float ws = dd * dd;
    float4 acc;
    acc.x = ws * hv.x; acc.y = ws * hv.y; acc.z = ws * hv.z; acc.w = ws * hv.w;

    const int beg = g_off[node];
    const int end = g_off[node + 1];
    int i = beg;
    for (; i + 3 < end; i += 4) {
        int   s[4];
        float w[4];
        float4 v[4];
#pragma unroll
        for (int u = 0; u < 4; u++) s[u] = g_elist[i + u];
#pragma unroll
        for (int u = 0; u < 4; u++) w[u] = dd * g_dinv[s[u]];
#pragma unroll
        for (int u = 0; u < 4; u++) v[u] = h4[(size_t)s[u] * 32 + lane];
#pragma unroll
        for (int u = 0; u < 4; u++) {
            acc.x = fmaf(w[u], v[u].x, acc.x);
            acc.y = fmaf(w[u], v[u].y, acc.y);
            acc.z = fmaf(w[u], v[u].z, acc.z);
            acc.w = fmaf(w[u], v[u].w, acc.w);
        }
    }
    for (; i < end; i++) {
        const int s = g_elist[i];
        const float w = dd * g_dinv[s];
        const float4 v = h4[(size_t)s * 32 + lane];
        acc.x = fmaf(w, v.x, acc.x);
        acc.y = fmaf(w, v.y, acc.y);
        acc.z = fmaf(w, v.z, acc.z);
        acc.w = fmaf(w, v.w, acc.w);
    }

    const float4 bv = reinterpret_cast<const float4*>(bias)[lane];
    acc.x = fmaxf(acc.x + bv.x, 0.f);
    acc.y = fmaxf(acc.y + bv.y, 0.f);
    acc.z = fmaxf(acc.z + bv.z, 0.f);
    acc.w = fmaxf(acc.w + bv.w, 0.f);
    g_bufB4[(size_t)node * 32 + lane] = acc;
}

// ---------------- pooling: sorted batch ids -> register accumulate, flush on change ----------------
#define POOL_NODES_PER_BLOCK 128
__global__ __launch_bounds__(128)
void pool_kernel(const int* __restrict__ batch, int N) {
    const int n0 = blockIdx.x * POOL_NODES_PER_BLOCK;
    const int n1 = min(n0 + POOL_NODES_PER_BLOCK, N);
    const int d = threadIdx.x;
    const float* __restrict__ h = reinterpret_cast<const float*>(g_bufB4);

    float acc = 0.f, c = 0.f;
    int curg = -1;
    for (int n = n0; n < n1; n++) {
        const int g = batch[n];
        if (g != curg) {
            if (curg >= 0) {
                atomicAdd(&g_pool[curg * 128 + d], acc);
                if (d == 0) atomicAdd(&g_gcnt[curg], c);
            }
            curg = g; acc = 0.f; c = 0.f;
        }
        acc += h[(size_t)n * 128 + d];
        c += 1.f;
    }
    if (curg >= 0) {
        atomicAdd(&g_pool[curg * 128 + d], acc);
        if (d == 0) atomicAdd(&g_gcnt[curg], c);
    }
}

// ---------------- FC head ----------------
__global__ __launch_bounds__(128)
void fc_kernel(const float* __restrict__ W, const float* __restrict__ b,
               float* __restrict__ out) {
    __shared__ float row[128];
    const int g = blockIdx.x;
    const int j = threadIdx.x;
    const float inv = 1.0f / fmaxf(g_gcnt[g], 1.0f);
    row[j] = g_pool[g * 128 + j] * inv;
    __syncthreads();
    float acc = b[j];
#pragma unroll
    for (int k = 0; k < 128; k++)
        acc = fmaf(row[k], W[k * 128 + j], acc);
    out[g * 128 + j] = acc;
}

// ---------------- launch ----------------
extern "C" void kernel_launch(void* const* d_in, const int* in_sizes, int n_in,
                              void* d_out, int out_size) {
    const float* x   = (const float*)d_in[0];
    const int*   ei  = (const int*)d_in[1];    // int32 (JAX x64 disabled)
    const int*   bat = (const int*)d_in[2];
    const float* W1  = (const float*)d_in[3];
    const float* b1  = (const float*)d_in[4];
    const float* W2  = (const float*)d_in[5];
    const float* b2  = (const float*)d_in[6];
    const float* Wfc = (const float*)d_in[7];
    const float* bfc = (const float*)d_in[8];
    float*       out = (float*)d_out;

    const int N = in_sizes[2];
    const int E = in_sizes[1] / 2;
    const int* src = ei;
    const int* dst = ei + E;

    const int gemm_blocks = (N + 127) / 128;
    const int agg_blocks  = (N * 32 + 255) / 256;   // warp per node

    // --- CSR build interleaved with independent GEMM1 ---
    // sgemm1 (x@W1 -> bufA) has no dependency on the CSR build; placed 4th so
    // the ncu capture window (4th launch) profiles the GEMM.
    zero_misc_kernel<<<1184, 256>>>();                     // 1
    count_kernel<<<(E + 255) / 256, 256>>>(dst, E);        // 2
    scanA_kernel<<<SCAN_NB, 256>>>();                      // 3
    sgemm128_kernel<<<gemm_blocks, 256>>>(x, 1, W1, N);    // 4  <- profiled
    scanB_kernel<<<1, 128>>>();                            // 5
    scanC_kernel<<<SCAN_NB, 256>>>();                      // 6
    fill_kernel<<<(E + 255) / 256, 256>>>(src, dst, E);    // 7

    // --- layer 1 aggregation ---
    agg_gather_kernel<<<agg_blocks, 256>>>(b1);            // 8

    // --- layer 2 ---
    sgemm128_kernel<<<gemm_blocks, 256>>>(nullptr, 0, W2, N); // 9
    agg_gather_kernel<<<agg_blocks, 256>>>(b2);               // 10

    // --- pool + fc ---
    pool_kernel<<<(N + POOL_NODES_PER_BLOCK - 1) / POOL_NODES_PER_BLOCK, 128>>>(bat, N); // 11
    fc_kernel<<<NGRAPH, 128>>>(Wfc, bfc, out);                // 12
}